// round 14
// baseline (speedup 1.0000x reference)
#include <cuda_runtime.h>
#include <cuda_bf16.h>

// ---------------- problem constants (fixed shapes) ----------------
#define N_SRC1 200000
#define N_DST1 50000
#define N_DST2 10000
#define E1     2000000
#define E2     400000
#define IN_F   128
#define H_F    256
#define N_CLS  47

#define PAD1   50048   // N_DST1 padded to multiple of 128
#define PN     48      // padded layer-2 projected width

// ---------------- scratch (device globals; zero-initialized) ----------------
__device__ int   g_is64;
__device__ int   g_off1[N_DST1 + 1];
__device__ int   g_off2[N_DST2 + 1];
__device__ float g_hneigh1[(size_t)PAD1 * IN_F];   // layer1 mean-aggregated feats
__device__ float g_h[(size_t)PAD1 * H_F];          // layer1 output (relu'd)
__device__ float g_p[(size_t)PAD1 * PN];           // h @ Wneigh2 (projected, padded)
__device__ float g_pagg[(size_t)N_DST2 * PN];      // mean-aggregated p
// W concat transposed to [n=256][k=256] (k = concat(Wself k, Wneigh k)), bf16 hi/lo
__device__ __align__(16) unsigned short g_bt_hi[256 * 256];
__device__ __align__(16) unsigned short g_bt_lo[256 * 256];

// ---------------- helpers ----------------
__device__ __forceinline__ unsigned smem_u32(const void* p) {
    unsigned a;
    asm("{ .reg .u64 t; cvta.to.shared.u64 t, %1; cvt.u32.u64 %0, t; }"
        : "=r"(a) : "l"(p));
    return a;
}
__device__ __forceinline__ void ldsm_x4(unsigned* r, unsigned addr) {
    asm volatile("ldmatrix.sync.aligned.m8n8.x4.shared.b16 {%0,%1,%2,%3}, [%4];"
                 : "=r"(r[0]), "=r"(r[1]), "=r"(r[2]), "=r"(r[3]) : "r"(addr));
}
__device__ __forceinline__ void mma_bf16(float* c, const unsigned* a,
                                         unsigned b0, unsigned b1) {
    asm volatile(
        "mma.sync.aligned.m16n8k16.row.col.f32.bf16.bf16.f32 "
        "{%0,%1,%2,%3}, {%4,%5,%6,%7}, {%8,%9}, {%0,%1,%2,%3};"
        : "+f"(c[0]), "+f"(c[1]), "+f"(c[2]), "+f"(c[3])
        : "r"(a[0]), "r"(a[1]), "r"(a[2]), "r"(a[3]), "r"(b0), "r"(b1));
}
__device__ __forceinline__ void cvt4(const float4& f, uint2& h, uint2& l) {
    __nv_bfloat16 h0 = __float2bfloat16(f.x), h1 = __float2bfloat16(f.y);
    __nv_bfloat16 h2 = __float2bfloat16(f.z), h3 = __float2bfloat16(f.w);
    __nv_bfloat16 l0 = __float2bfloat16(f.x - __bfloat162float(h0));
    __nv_bfloat16 l1 = __float2bfloat16(f.y - __bfloat162float(h1));
    __nv_bfloat16 l2 = __float2bfloat16(f.z - __bfloat162float(h2));
    __nv_bfloat16 l3 = __float2bfloat16(f.w - __bfloat162float(h3));
    h.x = (unsigned)__bfloat16_as_ushort(h0) | ((unsigned)__bfloat16_as_ushort(h1) << 16);
    h.y = (unsigned)__bfloat16_as_ushort(h2) | ((unsigned)__bfloat16_as_ushort(h3) << 16);
    l.x = (unsigned)__bfloat16_as_ushort(l0) | ((unsigned)__bfloat16_as_ushort(l1) << 16);
    l.y = (unsigned)__bfloat16_as_ushort(l2) | ((unsigned)__bfloat16_as_ushort(l3) << 16);
}

// ---------------- index dtype detection ----------------
// src1 values are uniform-random in [0, 200000). If int64, every odd 32-bit
// word (high word) is zero; if int32, odd words are random and essentially
// surely nonzero among 128 samples.
__global__ void detect_kernel(const int* __restrict__ src1_raw) {
    if (threadIdx.x == 0) {
        int nz = 0;
        for (int i = 1; i < 256; i += 2) nz |= (src1_raw[i] != 0);
        g_is64 = nz ? 0 : 1;
    }
}

// ---------------- CSR offsets via boundary scatter, 4 edges/thread ----------------
__device__ __forceinline__ void scatter4(const void* dst, int* off, int E,
                                         int ndst, int i, int is64) {
    int base = i * 4;
    int p;
    if (is64) p = (base == 0) ? -1 : (int)((const long long*)dst)[base - 1];
    else      p = (base == 0) ? -1 : ((const int*)dst)[base - 1];
    #pragma unroll
    for (int j = 0; j < 4; ++j) {
        int d = is64 ? (int)((const long long*)dst)[base + j]
                     : ((const int*)dst)[base + j];
        for (int t = p + 1; t <= d; ++t) off[t] = base + j;
        p = d;
    }
    if (base + 4 == E)
        for (int t = p + 1; t <= ndst; ++t) off[t] = E;
}

__global__ void offsets_kernel(const void* __restrict__ dst1,
                               const void* __restrict__ dst2) {
    int i = blockIdx.x * blockDim.x + threadIdx.x;   // E1/4 and E2/4 are exact
    int is64 = g_is64;
    if (i < E1 / 4) scatter4(dst1, g_off1, E1, N_DST1, i, is64);
    if (i < E2 / 4) scatter4(dst2, g_off2, E2, N_DST2, i, is64);
}

// ---------------- W concat transpose + bf16 hi/lo split ----------------
__global__ void wsplit_kernel(const float* __restrict__ Ws,
                              const float* __restrict__ Wn) {
    int n = blockIdx.x;          // 0..255
    int k = threadIdx.x;         // 0..255
    float v = (k < 128) ? Ws[k * H_F + n] : Wn[(k - 128) * H_F + n];
    __nv_bfloat16 hb = __float2bfloat16(v);
    __nv_bfloat16 lb = __float2bfloat16(v - __bfloat162float(hb));
    g_bt_hi[n * 256 + k] = __bfloat16_as_ushort(hb);
    g_bt_lo[n * 256 + k] = __bfloat16_as_ushort(lb);
}

// ---------------- layer-1 aggregation: one warp per dst row, MLP=8 ----------------
template <typename IT>
__device__ __forceinline__ void agg1_body(const float* __restrict__ x,
                                          const IT* __restrict__ src,
                                          int row, int lane) {
    int s = g_off1[row], e = g_off1[row + 1];
    float ax = 0.f, ay = 0.f, az = 0.f, aw = 0.f;
    int i = s;
    for (; i + 8 <= e; i += 8) {            // 8 gathers in flight
        int sx[8];
        #pragma unroll
        for (int j = 0; j < 8; ++j) sx[j] = (int)__ldg(src + i + j);
        float4 v[8];
        #pragma unroll
        for (int j = 0; j < 8; ++j)
            v[j] = __ldg((const float4*)(x + (size_t)sx[j] * IN_F) + lane);
        #pragma unroll
        for (int j = 0; j < 8; ++j) {
            ax += v[j].x; ay += v[j].y; az += v[j].z; aw += v[j].w;
        }
    }
    for (; i + 2 <= e; i += 2) {
        int s0 = (int)__ldg(src + i), s1 = (int)__ldg(src + i + 1);
        float4 v0 = __ldg((const float4*)(x + (size_t)s0 * IN_F) + lane);
        float4 v1 = __ldg((const float4*)(x + (size_t)s1 * IN_F) + lane);
        ax += v0.x + v1.x; ay += v0.y + v1.y;
        az += v0.z + v1.z; aw += v0.w + v1.w;
    }
    if (i < e) {
        int s0 = (int)__ldg(src + i);
        float4 v0 = __ldg((const float4*)(x + (size_t)s0 * IN_F) + lane);
        ax += v0.x; ay += v0.y; az += v0.z; aw += v0.w;
    }
    int deg = e - s;
    float sc = 1.0f / (float)(deg > 0 ? deg : 1);
    ((float4*)(g_hneigh1 + (size_t)row * IN_F))[lane] =
        make_float4(ax * sc, ay * sc, az * sc, aw * sc);
}

__global__ __launch_bounds__(256) void agg1_kernel(const float* __restrict__ x,
                                                   const void* __restrict__ srcv) {
    int row = (blockIdx.x * 256 + threadIdx.x) >> 5;
    if (row >= N_DST1) return;
    int lane = threadIdx.x & 31;
    if (g_is64) agg1_body<long long>(x, (const long long*)srcv, row, lane);
    else        agg1_body<int>(x, (const int*)srcv, row, lane);
}

// ---------------- layer-1 GEMM on tensor cores (mma.sync, bf16 3-term split) --
// g_h[m,n] = relu( Acat[m,:] @ Wcat[:,n] + b1[n] ),  Acat = [x | hneigh1].
// CTA tile 64m x 128n, 8 warps each m16 x n64, K=256 in 16 chunks of 16.
// 3 CTAs/SM (24 warps, 3 sync domains). smem row stride 40 bf16 (80 B);
// hi at cols 0-15, lo at cols 16-31.
__global__ __launch_bounds__(256, 3) void gemm1_kernel(
    const float* __restrict__ x, const float* __restrict__ bias1) {
    __shared__ __align__(16) unsigned short sA[2][64][40];
    __shared__ __align__(16) unsigned short sB[2][128][40];

    const int tid = threadIdx.x, wid = tid >> 5, lane = tid & 31;
    const int bm = blockIdx.x * 64, bn = blockIdx.y * 128;
    const int wm = (wid >> 1) * 16, wn = (wid & 1) * 64;

    float acc[8][4];
    #pragma unroll
    for (int j = 0; j < 8; j++)
        #pragma unroll
        for (int q = 0; q < 4; q++) acc[j][q] = 0.f;

    const int acr = tid >> 2;          // A conversion row 0..63
    const int ack = (tid & 3) * 4;     // A k offset 0,4,8,12
    const int bcr = tid >> 1;          // B copy row 0..127
    const int bck = (tid & 1) * 8;     // B k offset 0 or 8

    const unsigned aBase = smem_u32(&sA[0][0][0]);
    const unsigned bBase = smem_u32(&sB[0][0][0]);
    const int lr = lane & 15, lc = (lane >> 4) * 8;
    const unsigned offA = ((unsigned)(wm + lr) * 40 + lc) * 2;
    const unsigned offB = ((unsigned)(wn + lr) * 40 + lc) * 2;

    // prologue: chunk 0 -> regs -> buf 0
    float4 fa;
    uint4 pbh, pbl;
    {
        fa = __ldg((const float4*)(x + (size_t)(bm + acr) * IN_F + ack));
        const size_t bo = (size_t)(bn + bcr) * 256 + bck;
        pbh = *(const uint4*)(g_bt_hi + bo);
        pbl = *(const uint4*)(g_bt_lo + bo);
    }
    {
        uint2 h, l;
        cvt4(fa, h, l);
        *(uint2*)&sA[0][acr][ack]      = h;
        *(uint2*)&sA[0][acr][16 + ack] = l;
        *(uint4*)&sB[0][bcr][bck]      = pbh;
        *(uint4*)&sB[0][bcr][16 + bck] = pbl;
    }
    __syncthreads();

    #pragma unroll 1
    for (int ch = 0; ch < 16; ++ch) {
        const int buf = ch & 1;
        // prefetch chunk ch+1 into regs
        if (ch < 15) {
            const int chn = ch + 1;
            const float* Asel = (chn < 8) ? x : g_hneigh1;
            const int kc = (chn & 7) * 16;
            fa = __ldg((const float4*)(Asel + (size_t)(bm + acr) * IN_F + kc + ack));
            const size_t bo = (size_t)(bn + bcr) * 256 + chn * 16 + bck;
            pbh = *(const uint4*)(g_bt_hi + bo);
            pbl = *(const uint4*)(g_bt_lo + bo);
        }
        // compute on buf
        {
            const unsigned aB = aBase + buf * (64 * 40 * 2);
            const unsigned bB = bBase + buf * (128 * 40 * 2);
            unsigned ah[4], al[4];
            ldsm_x4(ah, aB + offA);
            ldsm_x4(al, aB + offA + 32);
            #pragma unroll
            for (int nt2 = 0; nt2 < 4; ++nt2) {
                unsigned bh[4], bl[4];
                ldsm_x4(bh, bB + offB + nt2 * 1280);
                ldsm_x4(bl, bB + offB + nt2 * 1280 + 32);
                float* c0 = acc[nt2 * 2];
                float* c1 = acc[nt2 * 2 + 1];
                mma_bf16(c0, ah, bh[0], bh[2]);
                mma_bf16(c0, ah, bl[0], bl[2]);
                mma_bf16(c0, al, bh[0], bh[2]);
                mma_bf16(c1, ah, bh[1], bh[3]);
                mma_bf16(c1, ah, bl[1], bl[3]);
                mma_bf16(c1, al, bh[1], bh[3]);
            }
        }
        // store chunk ch+1 -> buf^1 (its readers all passed the previous sync)
        if (ch < 15) {
            const int nb = buf ^ 1;
            uint2 h, l;
            cvt4(fa, h, l);
            *(uint2*)&sA[nb][acr][ack]      = h;
            *(uint2*)&sA[nb][acr][16 + ack] = l;
            *(uint4*)&sB[nb][bcr][bck]      = pbh;
            *(uint4*)&sB[nb][bcr][16 + bck] = pbl;
            __syncthreads();
        }
    }

    // epilogue: bias + relu -> g_h
    const int erow = lane >> 2;
    const int ecol = (lane & 3) * 2;
    #pragma unroll
    for (int nt = 0; nt < 8; ++nt) {
        const int col = bn + wn + nt * 8 + ecol;
        const float b0 = __ldg(bias1 + col);
        const float b1 = __ldg(bias1 + col + 1);
        const float* c = acc[nt];
        const int r0 = bm + wm + erow;
        float* p0 = g_h + (size_t)r0 * H_F + col;
        *(float2*)p0             = make_float2(fmaxf(c[0] + b0, 0.f), fmaxf(c[1] + b1, 0.f));
        *(float2*)(p0 + 8 * H_F) = make_float2(fmaxf(c[2] + b0, 0.f), fmaxf(c[3] + b1, 0.f));
    }
}

// ---------------- small GEMM body: [128 rows, K=256] @ W[256, 47] ----------------
// MODE 0: p = Arows @ W            -> g_p  (padded to PN cols, col 47 = 0)
// MODE 1: out = Arows @ W + g_pagg + b2 -> out (rows < N_DST2, cols < 47)
template <int MODE>
__device__ __forceinline__ void small_gemm_body(
    const float* __restrict__ Arows, const float* __restrict__ W,
    const float* __restrict__ bias2, float* __restrict__ outp, int bm) {
    extern __shared__ float sm[];
    float* sW = sm;                    // [256][49]
    float* As = sm + 256 * 49;         // [2][16][136]

    const int tid = threadIdx.x;
    const int tx = tid & 15;
    const int ty = tid >> 4;
    const int ar = tid >> 1;
    const int akc = (tid & 1) * 8;

    unsigned long long acc[4][3];
    #pragma unroll
    for (int i = 0; i < 4; i++)
        #pragma unroll
        for (int j = 0; j < 3; j++) acc[i][j] = 0ULL;

    for (int idx = tid; idx < 256 * N_CLS; idx += 256) {
        int k = idx / N_CLS, n = idx - k * N_CLS;
        sW[k * 49 + n] = W[idx];
    }
    sW[tid * 49 + 47] = 0.f;

    {
        const float* ap = Arows + (size_t)(bm + ar) * H_F + akc;
        float4 a0 = *(const float4*)ap;
        float4 a1 = *(const float4*)(ap + 4);
        As[(akc + 0) * 136 + ar] = a0.x; As[(akc + 1) * 136 + ar] = a0.y;
        As[(akc + 2) * 136 + ar] = a0.z; As[(akc + 3) * 136 + ar] = a0.w;
        As[(akc + 4) * 136 + ar] = a1.x; As[(akc + 5) * 136 + ar] = a1.y;
        As[(akc + 6) * 136 + ar] = a1.z; As[(akc + 7) * 136 + ar] = a1.w;
    }
    __syncthreads();

    #pragma unroll 1
    for (int ch = 0; ch < 16; ++ch) {
        int buf = ch & 1;
        float4 pa0, pa1;
        if (ch < 15) {
            const float* ap = Arows + (size_t)(bm + ar) * H_F + (ch + 1) * 16 + akc;
            pa0 = *(const float4*)ap;
            pa1 = *(const float4*)(ap + 4);
        }
        const float* Ab = As + buf * (16 * 136);
        #pragma unroll
        for (int k = 0; k < 16; ++k) {
            const float* arow = Ab + k * 136 + ty * 8;
            ulonglong2 p0 = *(const ulonglong2*)(arow + 0);
            ulonglong2 p1 = *(const ulonglong2*)(arow + 4);
            unsigned long long av[4] = {p0.x, p0.y, p1.x, p1.y};
            const float* wr = sW + (ch * 16 + k) * 49 + tx * 3;
            float b0 = wr[0], b1 = wr[1], b2v = wr[2];
            unsigned long long bd0, bd1, bd2;
            asm("mov.b64 %0, {%1, %1};" : "=l"(bd0) : "f"(b0));
            asm("mov.b64 %0, {%1, %1};" : "=l"(bd1) : "f"(b1));
            asm("mov.b64 %0, {%1, %1};" : "=l"(bd2) : "f"(b2v));
            #pragma unroll
            for (int i = 0; i < 4; i++) {
                asm("fma.rn.f32x2 %0, %1, %2, %0;" : "+l"(acc[i][0]) : "l"(av[i]), "l"(bd0));
                asm("fma.rn.f32x2 %0, %1, %2, %0;" : "+l"(acc[i][1]) : "l"(av[i]), "l"(bd1));
                asm("fma.rn.f32x2 %0, %1, %2, %0;" : "+l"(acc[i][2]) : "l"(av[i]), "l"(bd2));
            }
        }
        if (ch < 15) {
            float* Ad = As + (buf ^ 1) * (16 * 136);
            Ad[(akc + 0) * 136 + ar] = pa0.x; Ad[(akc + 1) * 136 + ar] = pa0.y;
            Ad[(akc + 2) * 136 + ar] = pa0.z; Ad[(akc + 3) * 136 + ar] = pa0.w;
            Ad[(akc + 4) * 136 + ar] = pa1.x; Ad[(akc + 5) * 136 + ar] = pa1.y;
            Ad[(akc + 6) * 136 + ar] = pa1.z; Ad[(akc + 7) * 136 + ar] = pa1.w;
            __syncthreads();
        }
    }

    #pragma unroll
    for (int i = 0; i < 4; i++) {
        int m0 = bm + ty * 8 + 2 * i;
        int m1 = m0 + 1;
        float lo[3], hi[3];
        #pragma unroll
        for (int j = 0; j < 3; j++)
            asm("mov.b64 {%0, %1}, %2;" : "=f"(lo[j]), "=f"(hi[j]) : "l"(acc[i][j]));
        if (MODE == 0) {
            #pragma unroll
            for (int j = 0; j < 3; j++) {
                g_p[(size_t)m0 * PN + tx * 3 + j] = lo[j];
                g_p[(size_t)m1 * PN + tx * 3 + j] = hi[j];
            }
        } else {
            if (m0 < N_DST2) {
                #pragma unroll
                for (int j = 0; j < 3; j++) {
                    int n = tx * 3 + j;
                    if (n < N_CLS)
                        outp[m0 * N_CLS + n] =
                            lo[j] + g_pagg[(size_t)m0 * PN + n] + __ldg(bias2 + n);
                }
            }
            if (m1 < N_DST2) {
                #pragma unroll
                for (int j = 0; j < 3; j++) {
                    int n = tx * 3 + j;
                    if (n < N_CLS)
                        outp[m1 * N_CLS + n] =
                            hi[j] + g_pagg[(size_t)m1 * PN + n] + __ldg(bias2 + n);
                }
            }
        }
    }
}

__global__ __launch_bounds__(256) void pgemm_kernel(const float* __restrict__ Wn2) {
    small_gemm_body<0>(g_h, Wn2, nullptr, nullptr, blockIdx.x * 128);
}
__global__ __launch_bounds__(256) void outgemm_kernel(const float* __restrict__ Ws2,
                                                      const float* __restrict__ b2,
                                                      float* __restrict__ out) {
    small_gemm_body<1>(g_h, Ws2, b2, out, blockIdx.x * 128);
}

// ---------------- layer-2 aggregation over projected feats (48 wide) ----------------
template <typename IT>
__device__ __forceinline__ void aggp_body(const IT* __restrict__ src, int g, int t) {
    int s = g_off2[g], e = g_off2[g + 1];
    bool act = (t < PN);
    size_t to = t;
    float acc = 0.f;
    int i = s;
    for (; i + 4 <= e; i += 4) {
        int s0 = (int)__ldg(src + i),     s1 = (int)__ldg(src + i + 1);
        int s2 = (int)__ldg(src + i + 2), s3 = (int)__ldg(src + i + 3);
        if (act) {
            float v0 = __ldg((const float*)g_p + (size_t)s0 * PN + to);
            float v1 = __ldg((const float*)g_p + (size_t)s1 * PN + to);
            float v2 = __ldg((const float*)g_p + (size_t)s2 * PN + to);
            float v3 = __ldg((const float*)g_p + (size_t)s3 * PN + to);
            acc += (v0 + v1) + (v2 + v3);
        }
    }
    for (; i < e; ++i) {
        int s0 = (int)__ldg(src + i);
        if (act) acc += __ldg((const float*)g_p + (size_t)s0 * PN + to);
    }
    int deg = e - s;
    float sc = 1.0f / (float)(deg > 0 ? deg : 1);
    if (act) g_pagg[(size_t)g * PN + t] = acc * sc;
}

__global__ __launch_bounds__(256) void aggp_kernel(const void* __restrict__ srcv) {
    int g = (blockIdx.x * 256 + threadIdx.x) >> 6;
    if (g >= N_DST2) return;
    int t = threadIdx.x & 63;
    if (g_is64) aggp_body<long long>((const long long*)srcv, g, t);
    else        aggp_body<int>((const int*)srcv, g, t);
}

// ---------------- launch ----------------
extern "C" void kernel_launch(void* const* d_in, const int* in_sizes, int n_in,
                              void* d_out, int out_size) {
    const float* x       = (const float*)d_in[0];
    const float* Wself1  = (const float*)d_in[1];
    const float* Wneigh1 = (const float*)d_in[2];
    const float* b1      = (const float*)d_in[3];
    const float* Wself2  = (const float*)d_in[4];
    const float* Wneigh2 = (const float*)d_in[5];
    const float* b2      = (const float*)d_in[6];
    const void*  src1    = d_in[7];
    const void*  dst1    = d_in[8];
    const void*  src2    = d_in[9];
    const void*  dst2    = d_in[10];
    float* out = (float*)d_out;

    const int SMALL_SMEM = (256 * 49 + 2 * 16 * 136) * 4;   // 67584 B
    cudaFuncSetAttribute(pgemm_kernel,
                         cudaFuncAttributeMaxDynamicSharedMemorySize, SMALL_SMEM);
    cudaFuncSetAttribute(outgemm_kernel,
                         cudaFuncAttributeMaxDynamicSharedMemorySize, SMALL_SMEM);

    detect_kernel<<<1, 32>>>((const int*)src1);
    offsets_kernel<<<(E1 / 4 + 255) / 256, 256>>>(dst1, dst2);
    wsplit_kernel<<<256, 256>>>(Wself1, Wneigh1);

    agg1_kernel<<<(N_DST1 + 7) / 8, 256>>>(x, src1);

    dim3 g1(PAD1 / 64, 2);              // 782 x 2 blocks
    gemm1_kernel<<<g1, 256>>>(x, b1);

    pgemm_kernel<<<PAD1 / 128, 256, SMALL_SMEM>>>(Wneigh2);

    aggp_kernel<<<(N_DST2 * 64) / 256, 256>>>(src2);

    outgemm_kernel<<<(N_DST2 + 127) / 128, 256, SMALL_SMEM>>>(Wself2, b2, out);
}

// round 15
// speedup vs baseline: 1.0993x; 1.0993x over previous
#include <cuda_runtime.h>
#include <cuda_bf16.h>

// ---------------- problem constants (fixed shapes) ----------------
#define N_SRC1 200000
#define N_DST1 50000
#define N_DST2 10000
#define E1     2000000
#define E2     400000
#define IN_F   128
#define H_F    256
#define N_CLS  47

#define PAD1   50048   // N_DST1 padded to multiple of 128
#define PN     48      // padded layer-2 projected width

// ---------------- scratch (device globals; zero-initialized) ----------------
__device__ int   g_is64;
__device__ int   g_off1[N_DST1 + 1];
__device__ int   g_off2[N_DST2 + 1];
__device__ float g_hneigh1[(size_t)PAD1 * IN_F];   // layer1 mean-aggregated feats
__device__ float g_h[(size_t)PAD1 * H_F];          // layer1 output (relu'd)
__device__ float g_p[(size_t)PAD1 * PN];           // h @ Wneigh2 (projected, padded)
__device__ float g_pagg[(size_t)N_DST2 * PN];      // mean-aggregated p
// layer-1 W concat transposed to [n=256][k=256], bf16 hi/lo
__device__ __align__(16) unsigned short g_bt_hi[256 * 256];
__device__ __align__(16) unsigned short g_bt_lo[256 * 256];
// layer-2 weights transposed to [n=64 pad][k=256], bf16 hi/lo
__device__ __align__(16) unsigned short g_w2n_hi[64 * 256];
__device__ __align__(16) unsigned short g_w2n_lo[64 * 256];
__device__ __align__(16) unsigned short g_w2s_hi[64 * 256];
__device__ __align__(16) unsigned short g_w2s_lo[64 * 256];

// ---------------- helpers ----------------
__device__ __forceinline__ unsigned smem_u32(const void* p) {
    unsigned a;
    asm("{ .reg .u64 t; cvta.to.shared.u64 t, %1; cvt.u32.u64 %0, t; }"
        : "=r"(a) : "l"(p));
    return a;
}
__device__ __forceinline__ void ldsm_x4(unsigned* r, unsigned addr) {
    asm volatile("ldmatrix.sync.aligned.m8n8.x4.shared.b16 {%0,%1,%2,%3}, [%4];"
                 : "=r"(r[0]), "=r"(r[1]), "=r"(r[2]), "=r"(r[3]) : "r"(addr));
}
__device__ __forceinline__ void mma_bf16(float* c, const unsigned* a,
                                         unsigned b0, unsigned b1) {
    asm volatile(
        "mma.sync.aligned.m16n8k16.row.col.f32.bf16.bf16.f32 "
        "{%0,%1,%2,%3}, {%4,%5,%6,%7}, {%8,%9}, {%0,%1,%2,%3};"
        : "+f"(c[0]), "+f"(c[1]), "+f"(c[2]), "+f"(c[3])
        : "r"(a[0]), "r"(a[1]), "r"(a[2]), "r"(a[3]), "r"(b0), "r"(b1));
}
__device__ __forceinline__ void cvt4(const float4& f, uint2& h, uint2& l) {
    __nv_bfloat16 h0 = __float2bfloat16(f.x), h1 = __float2bfloat16(f.y);
    __nv_bfloat16 h2 = __float2bfloat16(f.z), h3 = __float2bfloat16(f.w);
    __nv_bfloat16 l0 = __float2bfloat16(f.x - __bfloat162float(h0));
    __nv_bfloat16 l1 = __float2bfloat16(f.y - __bfloat162float(h1));
    __nv_bfloat16 l2 = __float2bfloat16(f.z - __bfloat162float(h2));
    __nv_bfloat16 l3 = __float2bfloat16(f.w - __bfloat162float(h3));
    h.x = (unsigned)__bfloat16_as_ushort(h0) | ((unsigned)__bfloat16_as_ushort(h1) << 16);
    h.y = (unsigned)__bfloat16_as_ushort(h2) | ((unsigned)__bfloat16_as_ushort(h3) << 16);
    l.x = (unsigned)__bfloat16_as_ushort(l0) | ((unsigned)__bfloat16_as_ushort(l1) << 16);
    l.y = (unsigned)__bfloat16_as_ushort(l2) | ((unsigned)__bfloat16_as_ushort(l3) << 16);
}

// ---------------- index dtype detection ----------------
// src1 values are uniform-random in [0, 200000). If int64, every odd 32-bit
// word (high word) is zero; if int32, odd words are random and essentially
// surely nonzero among 128 samples.
__global__ void detect_kernel(const int* __restrict__ src1_raw) {
    if (threadIdx.x == 0) {
        int nz = 0;
        for (int i = 1; i < 256; i += 2) nz |= (src1_raw[i] != 0);
        g_is64 = nz ? 0 : 1;
    }
}

// ---------------- CSR offsets via boundary scatter, 4 edges/thread ----------------
__device__ __forceinline__ void scatter4(const void* dst, int* off, int E,
                                         int ndst, int i, int is64) {
    int base = i * 4;
    int p;
    if (is64) p = (base == 0) ? -1 : (int)((const long long*)dst)[base - 1];
    else      p = (base == 0) ? -1 : ((const int*)dst)[base - 1];
    #pragma unroll
    for (int j = 0; j < 4; ++j) {
        int d = is64 ? (int)((const long long*)dst)[base + j]
                     : ((const int*)dst)[base + j];
        for (int t = p + 1; t <= d; ++t) off[t] = base + j;
        p = d;
    }
    if (base + 4 == E)
        for (int t = p + 1; t <= ndst; ++t) off[t] = E;
}

__global__ void offsets_kernel(const void* __restrict__ dst1,
                               const void* __restrict__ dst2) {
    int i = blockIdx.x * blockDim.x + threadIdx.x;   // E1/4 and E2/4 are exact
    int is64 = g_is64;
    if (i < E1 / 4) scatter4(dst1, g_off1, E1, N_DST1, i, is64);
    if (i < E2 / 4) scatter4(dst2, g_off2, E2, N_DST2, i, is64);
}

// ---------------- W preps: transpose + bf16 hi/lo split ----------------
__global__ void wsplit_kernel(const float* __restrict__ Ws,
                              const float* __restrict__ Wn) {
    int n = blockIdx.x;          // 0..255
    int k = threadIdx.x;         // 0..255
    float v = (k < 128) ? Ws[k * H_F + n] : Wn[(k - 128) * H_F + n];
    __nv_bfloat16 hb = __float2bfloat16(v);
    __nv_bfloat16 lb = __float2bfloat16(v - __bfloat162float(hb));
    g_bt_hi[n * 256 + k] = __bfloat16_as_ushort(hb);
    g_bt_lo[n * 256 + k] = __bfloat16_as_ushort(lb);
}

__global__ void wsplit2_kernel(const float* __restrict__ Wn2,
                               const float* __restrict__ Ws2) {
    int n = blockIdx.x;          // 0..63 (pad cols 47..63 -> 0)
    int k = threadIdx.x;         // 0..255
    float vn = (n < N_CLS) ? Wn2[k * N_CLS + n] : 0.f;
    float vs = (n < N_CLS) ? Ws2[k * N_CLS + n] : 0.f;
    __nv_bfloat16 nh = __float2bfloat16(vn);
    __nv_bfloat16 nl = __float2bfloat16(vn - __bfloat162float(nh));
    __nv_bfloat16 sh = __float2bfloat16(vs);
    __nv_bfloat16 sl = __float2bfloat16(vs - __bfloat162float(sh));
    g_w2n_hi[n * 256 + k] = __bfloat16_as_ushort(nh);
    g_w2n_lo[n * 256 + k] = __bfloat16_as_ushort(nl);
    g_w2s_hi[n * 256 + k] = __bfloat16_as_ushort(sh);
    g_w2s_lo[n * 256 + k] = __bfloat16_as_ushort(sl);
}

// ---------------- layer-1 aggregation: one warp per dst row, MLP=8 ----------------
template <typename IT>
__device__ __forceinline__ void agg1_body(const float* __restrict__ x,
                                          const IT* __restrict__ src,
                                          int row, int lane) {
    int s = g_off1[row], e = g_off1[row + 1];
    float ax = 0.f, ay = 0.f, az = 0.f, aw = 0.f;
    int i = s;
    for (; i + 8 <= e; i += 8) {            // 8 gathers in flight
        int sx[8];
        #pragma unroll
        for (int j = 0; j < 8; ++j) sx[j] = (int)__ldg(src + i + j);
        float4 v[8];
        #pragma unroll
        for (int j = 0; j < 8; ++j)
            v[j] = __ldg((const float4*)(x + (size_t)sx[j] * IN_F) + lane);
        #pragma unroll
        for (int j = 0; j < 8; ++j) {
            ax += v[j].x; ay += v[j].y; az += v[j].z; aw += v[j].w;
        }
    }
    for (; i + 2 <= e; i += 2) {
        int s0 = (int)__ldg(src + i), s1 = (int)__ldg(src + i + 1);
        float4 v0 = __ldg((const float4*)(x + (size_t)s0 * IN_F) + lane);
        float4 v1 = __ldg((const float4*)(x + (size_t)s1 * IN_F) + lane);
        ax += v0.x + v1.x; ay += v0.y + v1.y;
        az += v0.z + v1.z; aw += v0.w + v1.w;
    }
    if (i < e) {
        int s0 = (int)__ldg(src + i);
        float4 v0 = __ldg((const float4*)(x + (size_t)s0 * IN_F) + lane);
        ax += v0.x; ay += v0.y; az += v0.z; aw += v0.w;
    }
    int deg = e - s;
    float sc = 1.0f / (float)(deg > 0 ? deg : 1);
    ((float4*)(g_hneigh1 + (size_t)row * IN_F))[lane] =
        make_float4(ax * sc, ay * sc, az * sc, aw * sc);
}

__global__ __launch_bounds__(256) void agg1_kernel(const float* __restrict__ x,
                                                   const void* __restrict__ srcv) {
    int row = (blockIdx.x * 256 + threadIdx.x) >> 5;
    if (row >= N_DST1) return;
    int lane = threadIdx.x & 31;
    if (g_is64) agg1_body<long long>(x, (const long long*)srcv, row, lane);
    else        agg1_body<int>(x, (const int*)srcv, row, lane);
}

// ---------------- layer-1 GEMM on tensor cores (mma.sync, bf16 3-term split) --
// g_h[m,n] = relu( Acat[m,:] @ Wcat[:,n] + b1[n] ),  Acat = [x | hneigh1].
// Per CTA: 128m x 128n, 8 warps each m32 x n64, K in 16 chunks of 16. (R13 cfg)
__global__ __launch_bounds__(256, 2) void gemm1_kernel(
    const float* __restrict__ x, const float* __restrict__ bias1) {
    __shared__ __align__(16) unsigned short sA[2][128][40];
    __shared__ __align__(16) unsigned short sB[2][128][40];

    const int tid = threadIdx.x, wid = tid >> 5, lane = tid & 31;
    const int bm = blockIdx.x * 128, bn = blockIdx.y * 128;
    const int wm = (wid >> 1) * 32, wn = (wid & 1) * 64;

    float acc[2][8][4];
    #pragma unroll
    for (int i = 0; i < 2; i++)
        #pragma unroll
        for (int j = 0; j < 8; j++)
            #pragma unroll
            for (int q = 0; q < 4; q++) acc[i][j][q] = 0.f;

    const int cr = tid >> 1;            // conversion row / B n-row (0..127)
    const int ck = (tid & 1) * 8;       // k offset 0 or 8

    const unsigned aBase = smem_u32(&sA[0][0][0]);
    const unsigned bBase = smem_u32(&sB[0][0][0]);
    const int lr = lane & 15, lc = (lane >> 4) * 8;
    const unsigned offA = ((unsigned)(wm + lr) * 40 + lc) * 2;
    const unsigned offB = ((unsigned)(wn + lr) * 40 + lc) * 2;

    // prologue: chunk 0 -> regs -> buf 0
    float4 fa0, fa1; uint4 pbh, pbl;
    {
        const float* ap = x + (size_t)(bm + cr) * IN_F + ck;
        fa0 = __ldg((const float4*)ap);
        fa1 = __ldg((const float4*)ap + 1);
        const size_t bo = (size_t)(bn + cr) * 256 + ck;
        pbh = *(const uint4*)(g_bt_hi + bo);
        pbl = *(const uint4*)(g_bt_lo + bo);
    }
    {
        uint2 h0, l0, h1, l1;
        cvt4(fa0, h0, l0);
        cvt4(fa1, h1, l1);
        *(uint4*)&sA[0][cr][ck]      = make_uint4(h0.x, h0.y, h1.x, h1.y);
        *(uint4*)&sA[0][cr][16 + ck] = make_uint4(l0.x, l0.y, l1.x, l1.y);
        *(uint4*)&sB[0][cr][ck]      = pbh;
        *(uint4*)&sB[0][cr][16 + ck] = pbl;
    }
    __syncthreads();

    #pragma unroll 1
    for (int ch = 0; ch < 16; ++ch) {
        const int buf = ch & 1;
        if (ch < 15) {
            const int chn = ch + 1;
            const float* Asel = (chn < 8) ? x : g_hneigh1;
            const int kc = (chn & 7) * 16;
            const float* ap = Asel + (size_t)(bm + cr) * IN_F + kc + ck;
            fa0 = __ldg((const float4*)ap);
            fa1 = __ldg((const float4*)ap + 1);
            const size_t bo = (size_t)(bn + cr) * 256 + chn * 16 + ck;
            pbh = *(const uint4*)(g_bt_hi + bo);
            pbl = *(const uint4*)(g_bt_lo + bo);
        }
        {
            const unsigned aB = aBase + buf * 10240;
            const unsigned bB = bBase + buf * 10240;
            unsigned ah[2][4], al[2][4];
            #pragma unroll
            for (int mt = 0; mt < 2; ++mt) {
                ldsm_x4(ah[mt], aB + offA + mt * 1280);
                ldsm_x4(al[mt], aB + offA + mt * 1280 + 32);
            }
            #pragma unroll
            for (int nt2 = 0; nt2 < 4; ++nt2) {
                unsigned bh[4], bl[4];
                ldsm_x4(bh, bB + offB + nt2 * 1280);
                ldsm_x4(bl, bB + offB + nt2 * 1280 + 32);
                #pragma unroll
                for (int mt = 0; mt < 2; ++mt) {
                    float* c0 = acc[mt][nt2 * 2];
                    float* c1 = acc[mt][nt2 * 2 + 1];
                    mma_bf16(c0, ah[mt], bh[0], bh[2]);
                    mma_bf16(c0, ah[mt], bl[0], bl[2]);
                    mma_bf16(c0, al[mt], bh[0], bh[2]);
                    mma_bf16(c1, ah[mt], bh[1], bh[3]);
                    mma_bf16(c1, ah[mt], bl[1], bl[3]);
                    mma_bf16(c1, al[mt], bh[1], bh[3]);
                }
            }
        }
        if (ch < 15) {
            const int nb = buf ^ 1;
            uint2 h0, l0, h1, l1;
            cvt4(fa0, h0, l0);
            cvt4(fa1, h1, l1);
            *(uint4*)&sA[nb][cr][ck]      = make_uint4(h0.x, h0.y, h1.x, h1.y);
            *(uint4*)&sA[nb][cr][16 + ck] = make_uint4(l0.x, l0.y, l1.x, l1.y);
            *(uint4*)&sB[nb][cr][ck]      = pbh;
            *(uint4*)&sB[nb][cr][16 + ck] = pbl;
            __syncthreads();
        }
    }

    // epilogue: bias + relu -> g_h
    const int erow = lane >> 2;
    const int ecol = (lane & 3) * 2;
    #pragma unroll
    for (int nt = 0; nt < 8; ++nt) {
        const int col = bn + wn + nt * 8 + ecol;
        const float b0 = __ldg(bias1 + col);
        const float b1 = __ldg(bias1 + col + 1);
        #pragma unroll
        for (int mt = 0; mt < 2; ++mt) {
            const float* c = acc[mt][nt];
            const int r0 = bm + wm + mt * 16 + erow;
            float* p0 = g_h + (size_t)r0 * H_F + col;
            *(float2*)p0             = make_float2(fmaxf(c[0] + b0, 0.f), fmaxf(c[1] + b1, 0.f));
            *(float2*)(p0 + 8 * H_F) = make_float2(fmaxf(c[2] + b0, 0.f), fmaxf(c[3] + b1, 0.f));
        }
    }
}

// ---------------- layer-2 GEMMs on tensor cores: [128m, K=256] @ W2[256, 64] ----
// MODE 0: g_p[m, 0:48] = g_h[m,:] @ Wn2 (pad cols = 0)
// MODE 1: out[m, n<47] = g_h[m,:] @ Ws2 + g_pagg[m,n] + b2[n], m < N_DST2
// CTA 128m x 64n, 8 warps each m16 x n64.
template <int MODE>
__global__ __launch_bounds__(256, 2) void small_mma_kernel(
    const float* __restrict__ bias2, float* __restrict__ outp) {
    __shared__ __align__(16) unsigned short sA[2][128][40];
    __shared__ __align__(16) unsigned short sB[2][64][40];

    const unsigned short* wHi = (MODE == 0) ? g_w2n_hi : g_w2s_hi;
    const unsigned short* wLo = (MODE == 0) ? g_w2n_lo : g_w2s_lo;

    const int tid = threadIdx.x, wid = tid >> 5, lane = tid & 31;
    const int bm = blockIdx.x * 128;
    const int wm = wid * 16;

    float acc[8][4];
    #pragma unroll
    for (int j = 0; j < 8; j++)
        #pragma unroll
        for (int q = 0; q < 4; q++) acc[j][q] = 0.f;

    const int acr = tid >> 1;          // A conversion row 0..127
    const int ack = (tid & 1) * 8;     // k offset 0 or 8
    const int bcr = tid >> 2;          // B row 0..63
    const int bck = (tid & 3) * 4;     // k offset 0,4,8,12

    const unsigned aBase = smem_u32(&sA[0][0][0]);
    const unsigned bBase = smem_u32(&sB[0][0][0]);
    const int lr = lane & 15, lc = (lane >> 4) * 8;
    const unsigned offA = ((unsigned)(wm + lr) * 40 + lc) * 2;
    const unsigned offB = ((unsigned)lr * 40 + lc) * 2;

    // prologue: chunk 0
    float4 fa0, fa1; uint2 qbh, qbl;
    {
        const float* ap = g_h + (size_t)(bm + acr) * H_F + ack;
        fa0 = __ldg((const float4*)ap);
        fa1 = __ldg((const float4*)ap + 1);
        qbh = *(const uint2*)(wHi + (size_t)bcr * 256 + bck);
        qbl = *(const uint2*)(wLo + (size_t)bcr * 256 + bck);
    }
    {
        uint2 h0, l0, h1, l1;
        cvt4(fa0, h0, l0);
        cvt4(fa1, h1, l1);
        *(uint4*)&sA[0][acr][ack]      = make_uint4(h0.x, h0.y, h1.x, h1.y);
        *(uint4*)&sA[0][acr][16 + ack] = make_uint4(l0.x, l0.y, l1.x, l1.y);
        *(uint2*)&sB[0][bcr][bck]      = qbh;
        *(uint2*)&sB[0][bcr][16 + bck] = qbl;
    }
    __syncthreads();

    #pragma unroll 1
    for (int ch = 0; ch < 16; ++ch) {
        const int buf = ch & 1;
        if (ch < 15) {
            const int kc = (ch + 1) * 16;
            const float* ap = g_h + (size_t)(bm + acr) * H_F + kc + ack;
            fa0 = __ldg((const float4*)ap);
            fa1 = __ldg((const float4*)ap + 1);
            qbh = *(const uint2*)(wHi + (size_t)bcr * 256 + kc + bck);
            qbl = *(const uint2*)(wLo + (size_t)bcr * 256 + kc + bck);
        }
        {
            const unsigned aB = aBase + buf * (128 * 40 * 2);
            const unsigned bB = bBase + buf * (64 * 40 * 2);
            unsigned ah[4], al[4];
            ldsm_x4(ah, aB + offA);
            ldsm_x4(al, aB + offA + 32);
            #pragma unroll
            for (int nt2 = 0; nt2 < 4; ++nt2) {
                unsigned bh[4], bl[4];
                ldsm_x4(bh, bB + offB + nt2 * 1280);
                ldsm_x4(bl, bB + offB + nt2 * 1280 + 32);
                float* c0 = acc[nt2 * 2];
                float* c1 = acc[nt2 * 2 + 1];
                mma_bf16(c0, ah, bh[0], bh[2]);
                mma_bf16(c0, ah, bl[0], bl[2]);
                mma_bf16(c0, al, bh[0], bh[2]);
                mma_bf16(c1, ah, bh[1], bh[3]);
                mma_bf16(c1, ah, bl[1], bl[3]);
                mma_bf16(c1, al, bh[1], bh[3]);
            }
        }
        if (ch < 15) {
            const int nb = buf ^ 1;
            uint2 h0, l0, h1, l1;
            cvt4(fa0, h0, l0);
            cvt4(fa1, h1, l1);
            *(uint4*)&sA[nb][acr][ack]      = make_uint4(h0.x, h0.y, h1.x, h1.y);
            *(uint4*)&sA[nb][acr][16 + ack] = make_uint4(l0.x, l0.y, l1.x, l1.y);
            *(uint2*)&sB[nb][bcr][bck]      = qbh;
            *(uint2*)&sB[nb][bcr][16 + bck] = qbl;
            __syncthreads();
        }
    }

    // epilogue
    const int erow = lane >> 2;
    const int ecol = (lane & 3) * 2;
    #pragma unroll
    for (int nt = 0; nt < 8; ++nt) {
        const int col = nt * 8 + ecol;
        const float* c = acc[nt];
        const int r0 = bm + wm + erow;
        const int r1 = r0 + 8;
        if (MODE == 0) {
            if (col < PN) {
                *(float2*)(g_p + (size_t)r0 * PN + col) = make_float2(c[0], c[1]);
                *(float2*)(g_p + (size_t)r1 * PN + col) = make_float2(c[2], c[3]);
            }
        } else {
            if (col < N_CLS) {
                const float b0 = __ldg(bias2 + col);
                if (r0 < N_DST2) {
                    float v = c[0] + g_pagg[(size_t)r0 * PN + col] + b0;
                    outp[r0 * N_CLS + col] = v;
                }
                if (r1 < N_DST2) {
                    float v = c[2] + g_pagg[(size_t)r1 * PN + col] + b0;
                    outp[r1 * N_CLS + col] = v;
                }
                if (col + 1 < N_CLS) {
                    const float b1 = __ldg(bias2 + col + 1);
                    if (r0 < N_DST2)
                        outp[r0 * N_CLS + col + 1] =
                            c[1] + g_pagg[(size_t)r0 * PN + col + 1] + b1;
                    if (r1 < N_DST2)
                        outp[r1 * N_CLS + col + 1] =
                            c[3] + g_pagg[(size_t)r1 * PN + col + 1] + b1;
                }
            }
        }
    }
}

// ---------------- layer-2 aggregation over projected feats (48 wide) ----------------
template <typename IT>
__device__ __forceinline__ void aggp_body(const IT* __restrict__ src, int g, int t) {
    int s = g_off2[g], e = g_off2[g + 1];
    bool act = (t < PN);
    size_t to = t;
    float acc = 0.f;
    int i = s;
    for (; i + 4 <= e; i += 4) {
        int s0 = (int)__ldg(src + i),     s1 = (int)__ldg(src + i + 1);
        int s2 = (int)__ldg(src + i + 2), s3 = (int)__ldg(src + i + 3);
        if (act) {
            float v0 = __ldg((const float*)g_p + (size_t)s0 * PN + to);
            float v1 = __ldg((const float*)g_p + (size_t)s1 * PN + to);
            float v2 = __ldg((const float*)g_p + (size_t)s2 * PN + to);
            float v3 = __ldg((const float*)g_p + (size_t)s3 * PN + to);
            acc += (v0 + v1) + (v2 + v3);
        }
    }
    for (; i < e; ++i) {
        int s0 = (int)__ldg(src + i);
        if (act) acc += __ldg((const float*)g_p + (size_t)s0 * PN + to);
    }
    int deg = e - s;
    float sc = 1.0f / (float)(deg > 0 ? deg : 1);
    if (act) g_pagg[(size_t)g * PN + t] = acc * sc;
}

__global__ __launch_bounds__(256) void aggp_kernel(const void* __restrict__ srcv) {
    int g = (blockIdx.x * 256 + threadIdx.x) >> 6;
    if (g >= N_DST2) return;
    int t = threadIdx.x & 63;
    if (g_is64) aggp_body<long long>((const long long*)srcv, g, t);
    else        aggp_body<int>((const int*)srcv, g, t);
}

// ---------------- launch ----------------
extern "C" void kernel_launch(void* const* d_in, const int* in_sizes, int n_in,
                              void* d_out, int out_size) {
    const float* x       = (const float*)d_in[0];
    const float* Wself1  = (const float*)d_in[1];
    const float* Wneigh1 = (const float*)d_in[2];
    const float* b1      = (const float*)d_in[3];
    const float* Wself2  = (const float*)d_in[4];
    const float* Wneigh2 = (const float*)d_in[5];
    const float* b2      = (const float*)d_in[6];
    const void*  src1    = d_in[7];
    const void*  dst1    = d_in[8];
    const void*  src2    = d_in[9];
    const void*  dst2    = d_in[10];
    float* out = (float*)d_out;

    detect_kernel<<<1, 32>>>((const int*)src1);
    offsets_kernel<<<(E1 / 4 + 255) / 256, 256>>>(dst1, dst2);
    wsplit_kernel<<<256, 256>>>(Wself1, Wneigh1);
    wsplit2_kernel<<<64, 256>>>(Wneigh2, Wself2);

    agg1_kernel<<<(N_DST1 + 7) / 8, 256>>>(x, src1);

    dim3 g1(PAD1 / 128, 2);             // 391 x 2 blocks
    gemm1_kernel<<<g1, 256>>>(x, b1);

    small_mma_kernel<0><<<PAD1 / 128, 256>>>(nullptr, nullptr);     // p = h @ Wn2

    aggp_kernel<<<(N_DST2 * 64) / 256, 256>>>(src2);

    small_mma_kernel<1><<<(N_DST2 + 127) / 128, 256>>>(b2, out);    // out
}